// round 10
// baseline (speedup 1.0000x reference)
#include <cuda_runtime.h>
#include <cuda_bf16.h>
#include <cstdint>

#define EPSI 1e-7f

// ===========================================================================
// Scratch (__device__ globals; no allocation allowed).
// Qh/Ql,Kh/Kl,Vh/Vl: bf16 hi/lo, [B][nh][W][H][d].
// XVh/XVl: bf16 hi/lo, [B][nh][H][W][d].
// Xhi/Xlo: bf16 split of x, [pix][c].  Whi/Wlo: bf16 split of W^T, [p][f][c].
// ===========================================================================
__device__ __nv_bfloat16 g_Qh[33554432];
__device__ __nv_bfloat16 g_Ql[33554432];
__device__ __nv_bfloat16 g_Kh[33554432];
__device__ __nv_bfloat16 g_Kl[33554432];
__device__ __nv_bfloat16 g_Vh[33554432];
__device__ __nv_bfloat16 g_Vl[33554432];
__device__ __nv_bfloat16 g_XVh[33554432];
__device__ __nv_bfloat16 g_XVl[33554432];
__device__ __nv_bfloat16 g_Xhi[33554432];
__device__ __nv_bfloat16 g_Xlo[33554432];
__device__ __nv_bfloat16 g_Whi[786432];
__device__ __nv_bfloat16 g_Wlo[786432];

// ===========================================================================
// Helpers (sm_80-era tensor path; compiles on plain compute_103 target)
// ===========================================================================
__device__ __forceinline__ uint32_t smem_u32(const void* p) {
    uint32_t a;
    asm("{ .reg .u64 t; cvta.to.shared.u64 t, %1; cvt.u32.u64 %0, t; }"
        : "=r"(a) : "l"(p));
    return a;
}

#define LDMX4(r, addr) \
    asm volatile("ldmatrix.sync.aligned.m8n8.x4.shared.b16 {%0,%1,%2,%3}, [%4];" \
        : "=r"((r)[0]), "=r"((r)[1]), "=r"((r)[2]), "=r"((r)[3]) : "r"(addr))

#define LDMX4T(r, addr) \
    asm volatile("ldmatrix.sync.aligned.m8n8.x4.trans.shared.b16 {%0,%1,%2,%3}, [%4];" \
        : "=r"((r)[0]), "=r"((r)[1]), "=r"((r)[2]), "=r"((r)[3]) : "r"(addr))

__device__ __forceinline__ void mma16816(float* d, const uint32_t* a, const uint32_t* b) {
    asm volatile(
        "mma.sync.aligned.m16n8k16.row.col.f32.bf16.bf16.f32 "
        "{%0,%1,%2,%3}, {%4,%5,%6,%7}, {%8,%9}, {%0,%1,%2,%3};"
        : "+f"(d[0]), "+f"(d[1]), "+f"(d[2]), "+f"(d[3])
        : "r"(a[0]), "r"(a[1]), "r"(a[2]), "r"(a[3]), "r"(b[0]), "r"(b[1]));
}

#define CP16(dst, src) \
    asm volatile("cp.async.cg.shared.global [%0], [%1], 16;" \
        :: "r"(dst), "l"((const void*)(src)))

__device__ __forceinline__ uint32_t pack_bf16x2(float f0, float f1) {
    __nv_bfloat162 t = __floats2bfloat162_rn(f0, f1);   // x = f0 (low half)
    return *reinterpret_cast<uint32_t*>(&t);
}

// SW128 swizzle on byte offsets (rows are 128 B)
#define ASW(off) ((uint32_t)(off) ^ ((((uint32_t)(off)) >> 3) & 0x70u))

// ===========================================================================
// x -> bf16 hi/lo split
// ===========================================================================
__global__ void __launch_bounds__(256) xsplit_kernel(const float* __restrict__ x)
{
    const int i = blockIdx.x * 256 + threadIdx.x;
    float4 v = ((const float4*)x)[i];
    __nv_bfloat16 h0 = __float2bfloat16(v.x);
    __nv_bfloat16 h1 = __float2bfloat16(v.y);
    __nv_bfloat16 h2 = __float2bfloat16(v.z);
    __nv_bfloat16 h3 = __float2bfloat16(v.w);
    __nv_bfloat162 hp0; hp0.x = h0; hp0.y = h1;
    __nv_bfloat162 hp1; hp1.x = h2; hp1.y = h3;
    __nv_bfloat162 lp0;
    lp0.x = __float2bfloat16(v.x - __bfloat162float(h0));
    lp0.y = __float2bfloat16(v.y - __bfloat162float(h1));
    __nv_bfloat162 lp1;
    lp1.x = __float2bfloat16(v.z - __bfloat162float(h2));
    lp1.y = __float2bfloat16(v.w - __bfloat162float(h3));
    ((__nv_bfloat162*)g_Xhi)[i * 2 + 0] = hp0;
    ((__nv_bfloat162*)g_Xhi)[i * 2 + 1] = hp1;
    ((__nv_bfloat162*)g_Xlo)[i * 2 + 0] = lp0;
    ((__nv_bfloat162*)g_Xlo)[i * 2 + 1] = lp1;
}

// ===========================================================================
// W -> transposed bf16 hi/lo split: WT[p][f][c] = W_p[c][f]
// ===========================================================================
__global__ void __launch_bounds__(256) wsplit_kernel(
    const float* __restrict__ wq, const float* __restrict__ wk,
    const float* __restrict__ wv)
{
    const int idx = blockIdx.x * 256 + threadIdx.x;
    const int p = idx >> 18;
    const int f = (idx >> 9) & 511;
    const int c = idx & 511;
    const float* __restrict__ W = (p == 0) ? wq : (p == 1) ? wk : wv;
    const float v = W[c * 512 + f];
    __nv_bfloat16 h = __float2bfloat16(v);
    g_Whi[idx] = h;
    g_Wlo[idx] = __float2bfloat16(v - __bfloat162float(h));
}

// ===========================================================================
// Projection via warp-level mma.sync — 4-stage cp.async pipeline, BK=16.
// CTA tile 128x128, K=512 in 32 chunks of 16.  8 warps (4m x 2n).
// Stage = [Ahi|Alo|Bhi|Blo], each 128 rows x 48 B pitch (32 B data + 16 pad,
// conflict-free ldmatrix).  One __syncthreads per chunk; issue after barrier.
// ===========================================================================
#define PPITCH 48
#define PTILE  6144
#define PSTAGE 24576
#define PROJ_SMEM 98304

__global__ void __launch_bounds__(256, 2) proj_mma_kernel(
    const float* __restrict__ bq, const float* __restrict__ bk,
    const float* __restrict__ bv)
{
    extern __shared__ char smc[];
    const uint32_t sb = smem_u32(smc);

    const int tid  = threadIdx.x;
    const int lane = tid & 31;
    const int wid  = tid >> 5;
    const int wm   = wid & 3;
    const int wn   = wid >> 2;
    const int m0   = blockIdx.x * 128;
    const int n0   = blockIdx.y * 128;
    const int which = blockIdx.z;

    const __nv_bfloat16* __restrict__ Bh = g_Whi + which * 262144;
    const __nv_bfloat16* __restrict__ Bl = g_Wlo + which * 262144;
    const float* __restrict__ bias = (which == 0) ? bq : (which == 1) ? bk : bv;
    __nv_bfloat16* __restrict__ outH = (which == 0) ? g_Qh : (which == 1) ? g_Kh : g_Vh;
    __nv_bfloat16* __restrict__ outL = (which == 0) ? g_Ql : (which == 1) ? g_Kl : g_Vl;

    // loader mapping: row = tid>>1 (0..127), ch = tid&1 (two 16B chunks/row)
    const int lrow = tid >> 1;
    const int lch  = tid & 1;

    float acc[2][8][4];
#pragma unroll
    for (int a = 0; a < 2; a++)
#pragma unroll
        for (int b = 0; b < 8; b++)
#pragma unroll
            for (int c = 0; c < 4; c++) acc[a][b][c] = 0.0f;

    auto issue = [&](int c) {
        const int k0 = c * 16;
        const uint32_t st = sb + (c & 3) * PSTAGE;
        const uint32_t off = lrow * PPITCH + lch * 16;
        const int ga = (m0 + lrow) * 512 + k0 + lch * 8;
        const int gb = (n0 + lrow) * 512 + k0 + lch * 8;
        CP16(st + off,             g_Xhi + ga);
        CP16(st + PTILE + off,     g_Xlo + ga);
        CP16(st + 2 * PTILE + off, Bh + gb);
        CP16(st + 3 * PTILE + off, Bl + gb);
        asm volatile("cp.async.commit_group;");
    };

    issue(0); issue(1); issue(2);

    const int alr = lane & 15;
    const int alc = lane >> 4;
    const int blr = ((lane >> 4) << 3) + (lane & 7);
    const int blc = (lane >> 3) & 1;

    for (int c = 0; c < 32; c++) {
        asm volatile("cp.async.wait_group 2;");   // chunk c complete
        __syncthreads();                          // publish buffer c; frees (c-1)%4
        if (c < 29) issue(c + 3);                 // safe: after barrier

        const uint32_t st = sb + (c & 3) * PSTAGE;
        uint32_t a_hi[2][4], a_lo[2][4];
#pragma unroll
        for (int mt = 0; mt < 2; mt++) {
            const uint32_t ad = st + (wm * 32 + mt * 16 + alr) * PPITCH + alc * 16;
            LDMX4(a_hi[mt], ad);
            LDMX4(a_lo[mt], ad + PTILE);
        }
#pragma unroll
        for (int p = 0; p < 4; p++) {
            const uint32_t bd = st + 2 * PTILE
                              + (wn * 64 + p * 16 + blr) * PPITCH + blc * 16;
            uint32_t bh[4], bl[4];
            LDMX4(bh, bd);
            LDMX4(bl, bd + PTILE);
#pragma unroll
            for (int mt = 0; mt < 2; mt++) {
                mma16816(acc[mt][2 * p],     a_hi[mt], &bh[0]);
                mma16816(acc[mt][2 * p],     a_hi[mt], &bl[0]);
                mma16816(acc[mt][2 * p],     a_lo[mt], &bh[0]);
                mma16816(acc[mt][2 * p + 1], a_hi[mt], &bh[2]);
                mma16816(acc[mt][2 * p + 1], a_hi[mt], &bl[2]);
                mma16816(acc[mt][2 * p + 1], a_lo[mt], &bh[2]);
            }
        }
    }

    // ---- epilogue: bias, split hi/lo, scatter into [B][nh][W][H][d] ----
    const int g  = lane >> 2;
    const int tg = lane & 3;
#pragma unroll
    for (int mt = 0; mt < 2; mt++) {
#pragma unroll
        for (int half = 0; half < 2; half++) {
            const int pix = m0 + wm * 32 + mt * 16 + g + half * 8;
            const int b = pix >> 14;
            const int h = (pix >> 7) & 127;
            const int w = pix & 127;
#pragma unroll
            for (int nt = 0; nt < 8; nt++) {
                const int f  = n0 + wn * 64 + nt * 8 + tg * 2;
                const int nh = f >> 6;
                const int dd = f & 63;
                float2 bb = *(const float2*)(bias + f);
                const float ox = acc[mt][nt][half * 2 + 0] + bb.x;
                const float oy = acc[mt][nt][half * 2 + 1] + bb.y;
                __nv_bfloat16 hx = __float2bfloat16(ox);
                __nv_bfloat16 hy = __float2bfloat16(oy);
                __nv_bfloat162 hp; hp.x = hx; hp.y = hy;
                __nv_bfloat162 lp;
                lp.x = __float2bfloat16(ox - __bfloat162float(hx));
                lp.y = __float2bfloat16(oy - __bfloat162float(hy));
                const int off = (((b * 8 + nh) * 128 + w) * 128 + h) * 64 + dd;
                *(__nv_bfloat162*)(outH + off) = hp;
                *(__nv_bfloat162*)(outL + off) = lp;
            }
        }
    }
}

// ===========================================================================
// Tensor-core axial attention (unchanged from R9).
// smem 96 KB: Qh 0, Ql 16K, Kh 32K, Kl 48K, Vh 64K, Vl 80K; SW128-swizzled.
// ===========================================================================
#define AQHI 0
#define AQLO 16384
#define AKHI 32768
#define AKLO 49152
#define AVHI 65536
#define AVLO 81920
#define ATTN_SMEM 98304

__global__ void __launch_bounds__(256, 2) attn_mma_kernel(float* __restrict__ out, const int stage)
{
    extern __shared__ char sm[];
    const uint32_t sb = smem_u32(sm);

    const int tid  = threadIdx.x;
    const int lane = tid & 31;
    const int wid  = tid >> 5;
    const int x_   = blockIdx.x;
    const int b8n  = blockIdx.z * 8 + blockIdx.y;

    const __nv_bfloat16* __restrict__ Vhp = (stage == 1) ? g_Vh : g_XVh;
    const __nv_bfloat16* __restrict__ Vlp = (stage == 1) ? g_Vl : g_XVl;

    int qbase, rstride;
    if (stage == 1) {
        qbase   = (b8n * 128 + x_) * 8192;
        rstride = 64;
    } else {
        qbase   = b8n * 1048576 + x_ * 64;
        rstride = 8192;
    }
    const int vbase = (b8n * 128 + x_) * 8192;

    // ---- group 0: Q,K tiles (needed for S) ----
    for (int idx = tid; idx < 1024; idx += 256) {
        const int row = idx >> 3;
        const int ch  = idx & 7;
        const int qoff = qbase + row * rstride + ch * 8;
        const uint32_t dst = ASW(row * 128 + ch * 16);
        CP16(sb + AQHI + dst, g_Qh + qoff);
        CP16(sb + AQLO + dst, g_Ql + qoff);
        CP16(sb + AKHI + dst, g_Kh + qoff);
        CP16(sb + AKLO + dst, g_Kl + qoff);
    }
    asm volatile("cp.async.commit_group;");
    // ---- group 1: V tiles (needed only for O) ----
    for (int idx = tid; idx < 1024; idx += 256) {
        const int row = idx >> 3;
        const int ch  = idx & 7;
        const int voff = vbase + row * 64 + ch * 8;
        const uint32_t dst = ASW(row * 128 + ch * 16);
        CP16(sb + AVHI + dst, Vhp + voff);
        CP16(sb + AVLO + dst, Vlp + voff);
    }
    asm volatile("cp.async.commit_group;");

    asm volatile("cp.async.wait_group 1;");   // Q,K ready; V may still fly
    __syncthreads();

    // ---- S = Q * K^T  (warp strip m16 x N=128), bf16x3 ----
    float sacc[16][4];
#pragma unroll
    for (int j = 0; j < 16; j++)
#pragma unroll
        for (int c = 0; c < 4; c++) sacc[j][c] = 0.0f;

    const int m0w = wid * 16;
    const int alr = lane & 15;
    const int alc = lane >> 4;
    const int blr = ((lane >> 4) << 3) + (lane & 7);
    const int blc = (lane >> 3) & 1;

#pragma unroll
    for (int kt = 0; kt < 4; kt++) {
        uint32_t ahi[4], alo[4];
        const uint32_t aa = sb + AQHI + ASW((m0w + alr) * 128 + (kt * 2 + alc) * 16);
        LDMX4(ahi, aa);
        LDMX4(alo, aa + (AQLO - AQHI));
#pragma unroll
        for (int p = 0; p < 8; p++) {
            const uint32_t ba = sb + AKHI + ASW((p * 16 + blr) * 128 + (kt * 2 + blc) * 16);
            uint32_t bh[4], bl[4];
            LDMX4(bh, ba);
            LDMX4(bl, ba + (AKLO - AKHI));
            mma16816(sacc[2 * p],     ahi, &bh[0]);
            mma16816(sacc[2 * p],     ahi, &bl[0]);
            mma16816(sacc[2 * p],     alo, &bh[0]);
            mma16816(sacc[2 * p + 1], ahi, &bh[2]);
            mma16816(sacc[2 * p + 1], ahi, &bl[2]);
            mma16816(sacc[2 * p + 1], alo, &bh[2]);
        }
    }

    // ---- clip(+-(1-eps)), /8, softmax per row, clip [eps,1-eps] ----
    {
        const float lo = -1.0f + EPSI, hi = 1.0f - EPSI;
#pragma unroll
        for (int j = 0; j < 16; j++)
#pragma unroll
            for (int c = 0; c < 4; c++)
                sacc[j][c] = fminf(fmaxf(sacc[j][c], lo), hi) * 0.125f;

        float mx0 = -1e30f, mx1 = -1e30f;
#pragma unroll
        for (int j = 0; j < 16; j++) {
            mx0 = fmaxf(mx0, fmaxf(sacc[j][0], sacc[j][1]));
            mx1 = fmaxf(mx1, fmaxf(sacc[j][2], sacc[j][3]));
        }
        mx0 = fmaxf(mx0, __shfl_xor_sync(0xffffffffu, mx0, 1));
        mx0 = fmaxf(mx0, __shfl_xor_sync(0xffffffffu, mx0, 2));
        mx1 = fmaxf(mx1, __shfl_xor_sync(0xffffffffu, mx1, 1));
        mx1 = fmaxf(mx1, __shfl_xor_sync(0xffffffffu, mx1, 2));

        float s0 = 0.0f, s1 = 0.0f;
#pragma unroll
        for (int j = 0; j < 16; j++) {
            sacc[j][0] = __expf(sacc[j][0] - mx0);
            sacc[j][1] = __expf(sacc[j][1] - mx0);
            sacc[j][2] = __expf(sacc[j][2] - mx1);
            sacc[j][3] = __expf(sacc[j][3] - mx1);
            s0 += sacc[j][0] + sacc[j][1];
            s1 += sacc[j][2] + sacc[j][3];
        }
        s0 += __shfl_xor_sync(0xffffffffu, s0, 1);
        s0 += __shfl_xor_sync(0xffffffffu, s0, 2);
        s1 += __shfl_xor_sync(0xffffffffu, s1, 1);
        s1 += __shfl_xor_sync(0xffffffffu, s1, 2);
        const float i0 = 1.0f / s0, i1 = 1.0f / s1;
        const float alo2 = EPSI, ahi2 = 1.0f - EPSI;
#pragma unroll
        for (int j = 0; j < 16; j++) {
            sacc[j][0] = fminf(fmaxf(sacc[j][0] * i0, alo2), ahi2);
            sacc[j][1] = fminf(fmaxf(sacc[j][1] * i0, alo2), ahi2);
            sacc[j][2] = fminf(fmaxf(sacc[j][2] * i1, alo2), ahi2);
            sacc[j][3] = fminf(fmaxf(sacc[j][3] * i1, alo2), ahi2);
        }
    }

    asm volatile("cp.async.wait_group 0;");   // V ready
    __syncthreads();

    // ---- O = P * V  (m16 x N=64, K=128); V via ldmatrix.trans ----
    float oacc[8][4];
#pragma unroll
    for (int j = 0; j < 8; j++)
#pragma unroll
        for (int c = 0; c < 4; c++) oacc[j][c] = 0.0f;

    const int vr = (lane & 7) + ((lane >> 3) & 1) * 8;
    const int vc = lane >> 4;

#pragma unroll
    for (int jj = 0; jj < 8; jj++) {
        const int e = 2 * jj, o = 2 * jj + 1;
        uint32_t phi[4], plo[4];
        {
            float p00 = sacc[e][0], p01 = sacc[e][1];
            float p02 = sacc[e][2], p03 = sacc[e][3];
            float p10 = sacc[o][0], p11 = sacc[o][1];
            float p12 = sacc[o][2], p13 = sacc[o][3];
            __nv_bfloat16 h;
            float r0, r1;
            phi[0] = pack_bf16x2(p00, p01);
            h = __float2bfloat16(p00); r0 = p00 - __bfloat162float(h);
            h = __float2bfloat16(p01); r1 = p01 - __bfloat162float(h);
            plo[0] = pack_bf16x2(r0, r1);
            phi[1] = pack_bf16x2(p02, p03);
            h = __float2bfloat16(p02); r0 = p02 - __bfloat162float(h);
            h = __float2bfloat16(p03); r1 = p03 - __bfloat162float(h);
            plo[1] = pack_bf16x2(r0, r1);
            phi[2] = pack_bf16x2(p10, p11);
            h = __float2bfloat16(p10); r0 = p10 - __bfloat162float(h);
            h = __float2bfloat16(p11); r1 = p11 - __bfloat162float(h);
            plo[2] = pack_bf16x2(r0, r1);
            phi[3] = pack_bf16x2(p12, p13);
            h = __float2bfloat16(p12); r0 = p12 - __bfloat162float(h);
            h = __float2bfloat16(p13); r1 = p13 - __bfloat162float(h);
            plo[3] = pack_bf16x2(r0, r1);
        }
#pragma unroll
        for (int np = 0; np < 4; np++) {
            const uint32_t ba = sb + AVHI
                + ASW((jj * 16 + vr) * 128 + np * 32 + vc * 16);
            uint32_t bh[4], bl[4];
            LDMX4T(bh, ba);
            LDMX4T(bl, ba + (AVLO - AVHI));
            mma16816(oacc[2 * np],     phi, &bh[0]);
            mma16816(oacc[2 * np],     phi, &bl[0]);
            mma16816(oacc[2 * np],     plo, &bh[0]);
            mma16816(oacc[2 * np + 1], phi, &bh[2]);
            mma16816(oacc[2 * np + 1], phi, &bl[2]);
            mma16816(oacc[2 * np + 1], plo, &bh[2]);
        }
    }

    // ---- epilogue ----
    const int g  = lane >> 2;
    const int t4 = lane & 3;
    if (stage == 1) {
        const int base = b8n * 1048576 + x_ * 64;
#pragma unroll
        for (int nt = 0; nt < 8; nt++) {
            const int d = nt * 8 + t4 * 2;
#pragma unroll
            for (int half = 0; half < 2; half++) {
                const float ox = oacc[nt][half * 2 + 0];
                const float oy = oacc[nt][half * 2 + 1];
                __nv_bfloat16 hx = __float2bfloat16(ox);
                __nv_bfloat16 hy = __float2bfloat16(oy);
                __nv_bfloat162 hp; hp.x = hx; hp.y = hy;
                __nv_bfloat162 lp;
                lp.x = __float2bfloat16(ox - __bfloat162float(hx));
                lp.y = __float2bfloat16(oy - __bfloat162float(hy));
                const int off = base + (m0w + g + half * 8) * 8192 + d;
                *(__nv_bfloat162*)(g_XVh + off) = hp;
                *(__nv_bfloat162*)(g_XVl + off) = lp;
            }
        }
    } else {
        const int n = b8n & 7;
        const int b = b8n >> 3;
        const int base = (b * 128 + x_) * 65536 + n;
#pragma unroll
        for (int nt = 0; nt < 8; nt++) {
            const int d = nt * 8 + t4 * 2;
            out[base + (m0w + g) * 512 + d * 8]           = oacc[nt][0];
            out[base + (m0w + g) * 512 + (d + 1) * 8]     = oacc[nt][1];
            out[base + (m0w + g + 8) * 512 + d * 8]       = oacc[nt][2];
            out[base + (m0w + g + 8) * 512 + (d + 1) * 8] = oacc[nt][3];
        }
    }
}

// ---------------------------------------------------------------------------
extern "C" void kernel_launch(void* const* d_in, const int* in_sizes, int n_in,
                              void* d_out, int out_size)
{
    const float* x  = (const float*)d_in[0];
    const float* wq = (const float*)d_in[1];
    const float* bq = (const float*)d_in[2];
    const float* wk = (const float*)d_in[3];
    const float* bk = (const float*)d_in[4];
    const float* wv = (const float*)d_in[5];
    const float* bv = (const float*)d_in[6];
    float* out = (float*)d_out;

    cudaFuncSetAttribute((const void*)attn_mma_kernel,
                         cudaFuncAttributeMaxDynamicSharedMemorySize, ATTN_SMEM);
    cudaFuncSetAttribute((const void*)proj_mma_kernel,
                         cudaFuncAttributeMaxDynamicSharedMemorySize, PROJ_SMEM);

    xsplit_kernel<<<32768, 256>>>(x);
    wsplit_kernel<<<3072, 256>>>(wq, wk, wv);

    dim3 pg(512, 4, 3);
    proj_mma_kernel<<<pg, 256, PROJ_SMEM>>>(bq, bk, bv);

    dim3 ag(128, 8, 4);
    attn_mma_kernel<<<ag, 256, ATTN_SMEM>>>(out, 1);
    attn_mma_kernel<<<ag, 256, ATTN_SMEM>>>(out, 2);
}

// round 11
// speedup vs baseline: 1.0971x; 1.0971x over previous
#include <cuda_runtime.h>
#include <cuda_bf16.h>
#include <cstdint>

#define EPSI 1e-7f

// ===========================================================================
// Scratch (__device__ globals; no allocation allowed).
// Qh/Ql,Kh/Kl,Vh/Vl: bf16 hi/lo, [B][nh][W][H][d].
// XVh/XVl: bf16 hi/lo, [B][nh][H][W][d].
// Xhi/Xlo: bf16 split of x, [pix][c].  Whi/Wlo: bf16 split of W^T, [p][f][c].
// ===========================================================================
__device__ __nv_bfloat16 g_Qh[33554432];
__device__ __nv_bfloat16 g_Ql[33554432];
__device__ __nv_bfloat16 g_Kh[33554432];
__device__ __nv_bfloat16 g_Kl[33554432];
__device__ __nv_bfloat16 g_Vh[33554432];
__device__ __nv_bfloat16 g_Vl[33554432];
__device__ __nv_bfloat16 g_XVh[33554432];
__device__ __nv_bfloat16 g_XVl[33554432];
__device__ __nv_bfloat16 g_Xhi[33554432];
__device__ __nv_bfloat16 g_Xlo[33554432];
__device__ __nv_bfloat16 g_Whi[786432];
__device__ __nv_bfloat16 g_Wlo[786432];

// ===========================================================================
// Helpers (sm_80-era tensor path; compiles on plain compute_103 target)
// ===========================================================================
__device__ __forceinline__ uint32_t smem_u32(const void* p) {
    uint32_t a;
    asm("{ .reg .u64 t; cvta.to.shared.u64 t, %1; cvt.u32.u64 %0, t; }"
        : "=r"(a) : "l"(p));
    return a;
}

#define LDMX4(r, addr) \
    asm volatile("ldmatrix.sync.aligned.m8n8.x4.shared.b16 {%0,%1,%2,%3}, [%4];" \
        : "=r"((r)[0]), "=r"((r)[1]), "=r"((r)[2]), "=r"((r)[3]) : "r"(addr))

#define LDMX4T(r, addr) \
    asm volatile("ldmatrix.sync.aligned.m8n8.x4.trans.shared.b16 {%0,%1,%2,%3}, [%4];" \
        : "=r"((r)[0]), "=r"((r)[1]), "=r"((r)[2]), "=r"((r)[3]) : "r"(addr))

__device__ __forceinline__ void mma16816(float* d, const uint32_t* a, const uint32_t* b) {
    asm volatile(
        "mma.sync.aligned.m16n8k16.row.col.f32.bf16.bf16.f32 "
        "{%0,%1,%2,%3}, {%4,%5,%6,%7}, {%8,%9}, {%0,%1,%2,%3};"
        : "+f"(d[0]), "+f"(d[1]), "+f"(d[2]), "+f"(d[3])
        : "r"(a[0]), "r"(a[1]), "r"(a[2]), "r"(a[3]), "r"(b[0]), "r"(b[1]));
}

#define CP16(dst, src) \
    asm volatile("cp.async.cg.shared.global [%0], [%1], 16;" \
        :: "r"(dst), "l"((const void*)(src)))

__device__ __forceinline__ uint32_t pack_bf16x2(float f0, float f1) {
    __nv_bfloat162 t = __floats2bfloat162_rn(f0, f1);   // x = f0 (low half)
    return *reinterpret_cast<uint32_t*>(&t);
}

// SW128 swizzle on byte offsets (rows are 128 B)
#define ASW(off) ((uint32_t)(off) ^ ((((uint32_t)(off)) >> 3) & 0x70u))

// ===========================================================================
// x -> bf16 hi/lo split
// ===========================================================================
__global__ void __launch_bounds__(256) xsplit_kernel(const float* __restrict__ x)
{
    const int i = blockIdx.x * 256 + threadIdx.x;
    float4 v = ((const float4*)x)[i];
    __nv_bfloat16 h0 = __float2bfloat16(v.x);
    __nv_bfloat16 h1 = __float2bfloat16(v.y);
    __nv_bfloat16 h2 = __float2bfloat16(v.z);
    __nv_bfloat16 h3 = __float2bfloat16(v.w);
    __nv_bfloat162 hp0; hp0.x = h0; hp0.y = h1;
    __nv_bfloat162 hp1; hp1.x = h2; hp1.y = h3;
    __nv_bfloat162 lp0;
    lp0.x = __float2bfloat16(v.x - __bfloat162float(h0));
    lp0.y = __float2bfloat16(v.y - __bfloat162float(h1));
    __nv_bfloat162 lp1;
    lp1.x = __float2bfloat16(v.z - __bfloat162float(h2));
    lp1.y = __float2bfloat16(v.w - __bfloat162float(h3));
    ((__nv_bfloat162*)g_Xhi)[i * 2 + 0] = hp0;
    ((__nv_bfloat162*)g_Xhi)[i * 2 + 1] = hp1;
    ((__nv_bfloat162*)g_Xlo)[i * 2 + 0] = lp0;
    ((__nv_bfloat162*)g_Xlo)[i * 2 + 1] = lp1;
}

// ===========================================================================
// W -> transposed bf16 hi/lo split: WT[p][f][c] = W_p[c][f]
// ===========================================================================
__global__ void __launch_bounds__(256) wsplit_kernel(
    const float* __restrict__ wq, const float* __restrict__ wk,
    const float* __restrict__ wv)
{
    const int idx = blockIdx.x * 256 + threadIdx.x;
    const int p = idx >> 18;
    const int f = (idx >> 9) & 511;
    const int c = idx & 511;
    const float* __restrict__ W = (p == 0) ? wq : (p == 1) ? wk : wv;
    const float v = W[c * 512 + f];
    __nv_bfloat16 h = __float2bfloat16(v);
    g_Whi[idx] = h;
    g_Wlo[idx] = __float2bfloat16(v - __bfloat162float(h));
}

// ===========================================================================
// Projection via warp-level mma.sync (R9 pipeline: BK=32, depth-2, B frags
// consumed immediately, 2 CTAs/SM).  1-D grid with (which, n0) varying
// FASTEST so the 12 CTAs sharing one A-tile are launch-adjacent -> the
// 256 KB A-tile is read from HBM once and from L2 eleven times.
// ===========================================================================
#define TPITCH 80
#define TILE_B 10240
#define STAGE_B 40960
#define PROJ_SMEM 81920

__global__ void __launch_bounds__(256, 2) proj_mma_kernel(
    const float* __restrict__ bq, const float* __restrict__ bk,
    const float* __restrict__ bv)
{
    extern __shared__ char smc[];
    const uint32_t sb = smem_u32(smc);

    const int tid  = threadIdx.x;
    const int lane = tid & 31;
    const int wid  = tid >> 5;
    const int wm   = wid & 3;
    const int wn   = wid >> 2;

    // (which, n-tile) fastest, m-tile slowest
    const int bx    = blockIdx.x;
    const int which = bx % 3;
    const int n0    = ((bx / 3) & 3) * 128;
    const int m0    = (bx / 12) * 128;

    const __nv_bfloat16* __restrict__ Bh = g_Whi + which * 262144;
    const __nv_bfloat16* __restrict__ Bl = g_Wlo + which * 262144;
    const float* __restrict__ bias = (which == 0) ? bq : (which == 1) ? bk : bv;
    __nv_bfloat16* __restrict__ outH = (which == 0) ? g_Qh : (which == 1) ? g_Kh : g_Vh;
    __nv_bfloat16* __restrict__ outL = (which == 0) ? g_Ql : (which == 1) ? g_Kl : g_Vl;

    const int r0a = tid >> 2;
    const int ch  = tid & 3;

    float acc[2][8][4];
#pragma unroll
    for (int a = 0; a < 2; a++)
#pragma unroll
        for (int b = 0; b < 8; b++)
#pragma unroll
            for (int c = 0; c < 4; c++) acc[a][b][c] = 0.0f;

    auto issue = [&](int c) {
        const int k0 = c * 32;
        const uint32_t st = sb + (c & 1) * STAGE_B;
#pragma unroll
        for (int i = 0; i < 2; i++) {
            const int row = r0a + i * 64;
            const uint32_t off = row * TPITCH + ch * 16;
            const int ga = (m0 + row) * 512 + k0 + ch * 8;
            const int gb = (n0 + row) * 512 + k0 + ch * 8;
            CP16(st + off,              g_Xhi + ga);
            CP16(st + TILE_B + off,     g_Xlo + ga);
            CP16(st + 2 * TILE_B + off, Bh + gb);
            CP16(st + 3 * TILE_B + off, Bl + gb);
        }
        asm volatile("cp.async.commit_group;");
    };

    issue(0);
    for (int c = 0; c < 16; c++) {
        if (c < 15) {
            issue(c + 1);
            asm volatile("cp.async.wait_group 1;");
        } else {
            asm volatile("cp.async.wait_group 0;");
        }
        __syncthreads();

        const uint32_t st = sb + (c & 1) * STAGE_B;
#pragma unroll
        for (int ks = 0; ks < 2; ks++) {
            uint32_t a_hi[2][4], a_lo[2][4];
            const int al = lane & 15;
            const int ac = ks * 2 + (lane >> 4);
#pragma unroll
            for (int mt = 0; mt < 2; mt++) {
                const uint32_t ad = st + (wm * 32 + mt * 16 + al) * TPITCH + ac * 16;
                LDMX4(a_hi[mt], ad);
                LDMX4(a_lo[mt], ad + TILE_B);
            }
            const int br = (lane >> 4) * 8 + (lane & 7);
            const int bc = ks * 2 + ((lane >> 3) & 1);
#pragma unroll
            for (int p = 0; p < 4; p++) {
                const uint32_t bd = st + 2 * TILE_B
                                  + (wn * 64 + p * 16 + br) * TPITCH + bc * 16;
                uint32_t bh[4], bl[4];
                LDMX4(bh, bd);
                LDMX4(bl, bd + TILE_B);
#pragma unroll
                for (int mt = 0; mt < 2; mt++) {
                    mma16816(acc[mt][2 * p],     a_hi[mt], &bh[0]);
                    mma16816(acc[mt][2 * p],     a_hi[mt], &bl[0]);
                    mma16816(acc[mt][2 * p],     a_lo[mt], &bh[0]);
                    mma16816(acc[mt][2 * p + 1], a_hi[mt], &bh[2]);
                    mma16816(acc[mt][2 * p + 1], a_hi[mt], &bl[2]);
                    mma16816(acc[mt][2 * p + 1], a_lo[mt], &bh[2]);
                }
            }
        }
        __syncthreads();
    }

    // ---- epilogue: bias, split hi/lo, scatter into [B][nh][W][H][d] ----
    const int g  = lane >> 2;
    const int tg = lane & 3;
#pragma unroll
    for (int mt = 0; mt < 2; mt++) {
#pragma unroll
        for (int half = 0; half < 2; half++) {
            const int pix = m0 + wm * 32 + mt * 16 + g + half * 8;
            const int b = pix >> 14;
            const int h = (pix >> 7) & 127;
            const int w = pix & 127;
#pragma unroll
            for (int nt = 0; nt < 8; nt++) {
                const int f  = n0 + wn * 64 + nt * 8 + tg * 2;
                const int nh = f >> 6;
                const int dd = f & 63;
                float2 bb = *(const float2*)(bias + f);
                const float ox = acc[mt][nt][half * 2 + 0] + bb.x;
                const float oy = acc[mt][nt][half * 2 + 1] + bb.y;
                __nv_bfloat16 hx = __float2bfloat16(ox);
                __nv_bfloat16 hy = __float2bfloat16(oy);
                __nv_bfloat162 hp; hp.x = hx; hp.y = hy;
                __nv_bfloat162 lp;
                lp.x = __float2bfloat16(ox - __bfloat162float(hx));
                lp.y = __float2bfloat16(oy - __bfloat162float(hy));
                const int off = (((b * 8 + nh) * 128 + w) * 128 + h) * 64 + dd;
                *(__nv_bfloat162*)(outH + off) = hp;
                *(__nv_bfloat162*)(outL + off) = lp;
            }
        }
    }
}

// ===========================================================================
// Tensor-core axial attention (unchanged from R9).
// smem 96 KB: Qh 0, Ql 16K, Kh 32K, Kl 48K, Vh 64K, Vl 80K; SW128-swizzled.
// ===========================================================================
#define AQHI 0
#define AQLO 16384
#define AKHI 32768
#define AKLO 49152
#define AVHI 65536
#define AVLO 81920
#define ATTN_SMEM 98304

__global__ void __launch_bounds__(256, 2) attn_mma_kernel(float* __restrict__ out, const int stage)
{
    extern __shared__ char sm[];
    const uint32_t sb = smem_u32(sm);

    const int tid  = threadIdx.x;
    const int lane = tid & 31;
    const int wid  = tid >> 5;
    const int x_   = blockIdx.x;
    const int b8n  = blockIdx.z * 8 + blockIdx.y;

    const __nv_bfloat16* __restrict__ Vhp = (stage == 1) ? g_Vh : g_XVh;
    const __nv_bfloat16* __restrict__ Vlp = (stage == 1) ? g_Vl : g_XVl;

    int qbase, rstride;
    if (stage == 1) {
        qbase   = (b8n * 128 + x_) * 8192;
        rstride = 64;
    } else {
        qbase   = b8n * 1048576 + x_ * 64;
        rstride = 8192;
    }
    const int vbase = (b8n * 128 + x_) * 8192;

    // ---- group 0: Q,K tiles (needed for S) ----
    for (int idx = tid; idx < 1024; idx += 256) {
        const int row = idx >> 3;
        const int ch  = idx & 7;
        const int qoff = qbase + row * rstride + ch * 8;
        const uint32_t dst = ASW(row * 128 + ch * 16);
        CP16(sb + AQHI + dst, g_Qh + qoff);
        CP16(sb + AQLO + dst, g_Ql + qoff);
        CP16(sb + AKHI + dst, g_Kh + qoff);
        CP16(sb + AKLO + dst, g_Kl + qoff);
    }
    asm volatile("cp.async.commit_group;");
    // ---- group 1: V tiles (needed only for O) ----
    for (int idx = tid; idx < 1024; idx += 256) {
        const int row = idx >> 3;
        const int ch  = idx & 7;
        const int voff = vbase + row * 64 + ch * 8;
        const uint32_t dst = ASW(row * 128 + ch * 16);
        CP16(sb + AVHI + dst, Vhp + voff);
        CP16(sb + AVLO + dst, Vlp + voff);
    }
    asm volatile("cp.async.commit_group;");

    asm volatile("cp.async.wait_group 1;");   // Q,K ready; V may still fly
    __syncthreads();

    // ---- S = Q * K^T  (warp strip m16 x N=128), bf16x3 ----
    float sacc[16][4];
#pragma unroll
    for (int j = 0; j < 16; j++)
#pragma unroll
        for (int c = 0; c < 4; c++) sacc[j][c] = 0.0f;

    const int m0w = wid * 16;
    const int alr = lane & 15;
    const int alc = lane >> 4;
    const int blr = ((lane >> 4) << 3) + (lane & 7);
    const int blc = (lane >> 3) & 1;

#pragma unroll
    for (int kt = 0; kt < 4; kt++) {
        uint32_t ahi[4], alo[4];
        const uint32_t aa = sb + AQHI + ASW((m0w + alr) * 128 + (kt * 2 + alc) * 16);
        LDMX4(ahi, aa);
        LDMX4(alo, aa + (AQLO - AQHI));
#pragma unroll
        for (int p = 0; p < 8; p++) {
            const uint32_t ba = sb + AKHI + ASW((p * 16 + blr) * 128 + (kt * 2 + blc) * 16);
            uint32_t bh[4], bl[4];
            LDMX4(bh, ba);
            LDMX4(bl, ba + (AKLO - AKHI));
            mma16816(sacc[2 * p],     ahi, &bh[0]);
            mma16816(sacc[2 * p],     ahi, &bl[0]);
            mma16816(sacc[2 * p],     alo, &bh[0]);
            mma16816(sacc[2 * p + 1], ahi, &bh[2]);
            mma16816(sacc[2 * p + 1], ahi, &bl[2]);
            mma16816(sacc[2 * p + 1], alo, &bh[2]);
        }
    }

    // ---- clip(+-(1-eps)), /8, softmax per row, clip [eps,1-eps] ----
    {
        const float lo = -1.0f + EPSI, hi = 1.0f - EPSI;
#pragma unroll
        for (int j = 0; j < 16; j++)
#pragma unroll
            for (int c = 0; c < 4; c++)
                sacc[j][c] = fminf(fmaxf(sacc[j][c], lo), hi) * 0.125f;

        float mx0 = -1e30f, mx1 = -1e30f;
#pragma unroll
        for (int j = 0; j < 16; j++) {
            mx0 = fmaxf(mx0, fmaxf(sacc[j][0], sacc[j][1]));
            mx1 = fmaxf(mx1, fmaxf(sacc[j][2], sacc[j][3]));
        }
        mx0 = fmaxf(mx0, __shfl_xor_sync(0xffffffffu, mx0, 1));
        mx0 = fmaxf(mx0, __shfl_xor_sync(0xffffffffu, mx0, 2));
        mx1 = fmaxf(mx1, __shfl_xor_sync(0xffffffffu, mx1, 1));
        mx1 = fmaxf(mx1, __shfl_xor_sync(0xffffffffu, mx1, 2));

        float s0 = 0.0f, s1 = 0.0f;
#pragma unroll
        for (int j = 0; j < 16; j++) {
            sacc[j][0] = __expf(sacc[j][0] - mx0);
            sacc[j][1] = __expf(sacc[j][1] - mx0);
            sacc[j][2] = __expf(sacc[j][2] - mx1);
            sacc[j][3] = __expf(sacc[j][3] - mx1);
            s0 += sacc[j][0] + sacc[j][1];
            s1 += sacc[j][2] + sacc[j][3];
        }
        s0 += __shfl_xor_sync(0xffffffffu, s0, 1);
        s0 += __shfl_xor_sync(0xffffffffu, s0, 2);
        s1 += __shfl_xor_sync(0xffffffffu, s1, 1);
        s1 += __shfl_xor_sync(0xffffffffu, s1, 2);
        const float i0 = 1.0f / s0, i1 = 1.0f / s1;
        const float alo2 = EPSI, ahi2 = 1.0f - EPSI;
#pragma unroll
        for (int j = 0; j < 16; j++) {
            sacc[j][0] = fminf(fmaxf(sacc[j][0] * i0, alo2), ahi2);
            sacc[j][1] = fminf(fmaxf(sacc[j][1] * i0, alo2), ahi2);
            sacc[j][2] = fminf(fmaxf(sacc[j][2] * i1, alo2), ahi2);
            sacc[j][3] = fminf(fmaxf(sacc[j][3] * i1, alo2), ahi2);
        }
    }

    asm volatile("cp.async.wait_group 0;");   // V ready
    __syncthreads();

    // ---- O = P * V  (m16 x N=64, K=128); V via ldmatrix.trans ----
    float oacc[8][4];
#pragma unroll
    for (int j = 0; j < 8; j++)
#pragma unroll
        for (int c = 0; c < 4; c++) oacc[j][c] = 0.0f;

    const int vr = (lane & 7) + ((lane >> 3) & 1) * 8;
    const int vc = lane >> 4;

#pragma unroll
    for (int jj = 0; jj < 8; jj++) {
        const int e = 2 * jj, o = 2 * jj + 1;
        uint32_t phi[4], plo[4];
        {
            float p00 = sacc[e][0], p01 = sacc[e][1];
            float p02 = sacc[e][2], p03 = sacc[e][3];
            float p10 = sacc[o][0], p11 = sacc[o][1];
            float p12 = sacc[o][2], p13 = sacc[o][3];
            __nv_bfloat16 h;
            float r0, r1;
            phi[0] = pack_bf16x2(p00, p01);
            h = __float2bfloat16(p00); r0 = p00 - __bfloat162float(h);
            h = __float2bfloat16(p01); r1 = p01 - __bfloat162float(h);
            plo[0] = pack_bf16x2(r0, r1);
            phi[1] = pack_bf16x2(p02, p03);
            h = __float2bfloat16(p02); r0 = p02 - __bfloat162float(h);
            h = __float2bfloat16(p03); r1 = p03 - __bfloat162float(h);
            plo[1] = pack_bf16x2(r0, r1);
            phi[2] = pack_bf16x2(p10, p11);
            h = __float2bfloat16(p10); r0 = p10 - __bfloat162float(h);
            h = __float2bfloat16(p11); r1 = p11 - __bfloat162float(h);
            plo[2] = pack_bf16x2(r0, r1);
            phi[3] = pack_bf16x2(p12, p13);
            h = __float2bfloat16(p12); r0 = p12 - __bfloat162float(h);
            h = __float2bfloat16(p13); r1 = p13 - __bfloat162float(h);
            plo[3] = pack_bf16x2(r0, r1);
        }
#pragma unroll
        for (int np = 0; np < 4; np++) {
            const uint32_t ba = sb + AVHI
                + ASW((jj * 16 + vr) * 128 + np * 32 + vc * 16);
            uint32_t bh[4], bl[4];
            LDMX4T(bh, ba);
            LDMX4T(bl, ba + (AVLO - AVHI));
            mma16816(oacc[2 * np],     phi, &bh[0]);
            mma16816(oacc[2 * np],     phi, &bl[0]);
            mma16816(oacc[2 * np],     plo, &bh[0]);
            mma16816(oacc[2 * np + 1], phi, &bh[2]);
            mma16816(oacc[2 * np + 1], phi, &bl[2]);
            mma16816(oacc[2 * np + 1], plo, &bh[2]);
        }
    }

    // ---- epilogue ----
    const int g  = lane >> 2;
    const int t4 = lane & 3;
    if (stage == 1) {
        const int base = b8n * 1048576 + x_ * 64;
#pragma unroll
        for (int nt = 0; nt < 8; nt++) {
            const int d = nt * 8 + t4 * 2;
#pragma unroll
            for (int half = 0; half < 2; half++) {
                const float ox = oacc[nt][half * 2 + 0];
                const float oy = oacc[nt][half * 2 + 1];
                __nv_bfloat16 hx = __float2bfloat16(ox);
                __nv_bfloat16 hy = __float2bfloat16(oy);
                __nv_bfloat162 hp; hp.x = hx; hp.y = hy;
                __nv_bfloat162 lp;
                lp.x = __float2bfloat16(ox - __bfloat162float(hx));
                lp.y = __float2bfloat16(oy - __bfloat162float(hy));
                const int off = base + (m0w + g + half * 8) * 8192 + d;
                *(__nv_bfloat162*)(g_XVh + off) = hp;
                *(__nv_bfloat162*)(g_XVl + off) = lp;
            }
        }
    } else {
        const int n = b8n & 7;
        const int b = b8n >> 3;
        const int base = (b * 128 + x_) * 65536 + n;
#pragma unroll
        for (int nt = 0; nt < 8; nt++) {
            const int d = nt * 8 + t4 * 2;
            out[base + (m0w + g) * 512 + d * 8]           = oacc[nt][0];
            out[base + (m0w + g) * 512 + (d + 1) * 8]     = oacc[nt][1];
            out[base + (m0w + g + 8) * 512 + d * 8]       = oacc[nt][2];
            out[base + (m0w + g + 8) * 512 + (d + 1) * 8] = oacc[nt][3];
        }
    }
}

// ---------------------------------------------------------------------------
extern "C" void kernel_launch(void* const* d_in, const int* in_sizes, int n_in,
                              void* d_out, int out_size)
{
    const float* x  = (const float*)d_in[0];
    const float* wq = (const float*)d_in[1];
    const float* bq = (const float*)d_in[2];
    const float* wk = (const float*)d_in[3];
    const float* bk = (const float*)d_in[4];
    const float* wv = (const float*)d_in[5];
    const float* bv = (const float*)d_in[6];
    float* out = (float*)d_out;

    cudaFuncSetAttribute((const void*)attn_mma_kernel,
                         cudaFuncAttributeMaxDynamicSharedMemorySize, ATTN_SMEM);
    cudaFuncSetAttribute((const void*)proj_mma_kernel,
                         cudaFuncAttributeMaxDynamicSharedMemorySize, PROJ_SMEM);

    xsplit_kernel<<<32768, 256>>>(x);
    wsplit_kernel<<<3072, 256>>>(wq, wk, wv);

    // 6144 CTAs: which fastest, then n-tile, then m-tile (L2 A-reuse)
    proj_mma_kernel<<<6144, 256, PROJ_SMEM>>>(bq, bk, bv);

    dim3 ag(128, 8, 4);
    attn_mma_kernel<<<ag, 256, ATTN_SMEM>>>(out, 1);
    attn_mma_kernel<<<ag, 256, ATTN_SMEM>>>(out, 2);
}

// round 12
// speedup vs baseline: 1.6764x; 1.5280x over previous
#include <cuda_runtime.h>
#include <cuda_bf16.h>
#include <cuda_fp16.h>
#include <cstdint>

#define EPSI 1e-7f

// ===========================================================================
// Scratch (__device__ globals; no allocation allowed).
// Qh/Ql,Kh/Kl,Vh/Vl: bf16 hi/lo, [B][nh][W][H][d].
// XVh/XVl: bf16 hi/lo, [B][nh][H][W][d].
// g_Xh: fp16 x, [pix][c].  g_Wh: fp16 W^T, [p][f][c].
// ===========================================================================
__device__ __nv_bfloat16 g_Qh[33554432];
__device__ __nv_bfloat16 g_Ql[33554432];
__device__ __nv_bfloat16 g_Kh[33554432];
__device__ __nv_bfloat16 g_Kl[33554432];
__device__ __nv_bfloat16 g_Vh[33554432];
__device__ __nv_bfloat16 g_Vl[33554432];
__device__ __nv_bfloat16 g_XVh[33554432];
__device__ __nv_bfloat16 g_XVl[33554432];
__device__ __half g_Xh[33554432];
__device__ __half g_Wh[786432];

// ===========================================================================
// Helpers (sm_80-era tensor path; compiles on plain compute_103 target)
// ===========================================================================
__device__ __forceinline__ uint32_t smem_u32(const void* p) {
    uint32_t a;
    asm("{ .reg .u64 t; cvta.to.shared.u64 t, %1; cvt.u32.u64 %0, t; }"
        : "=r"(a) : "l"(p));
    return a;
}

#define LDMX4(r, addr) \
    asm volatile("ldmatrix.sync.aligned.m8n8.x4.shared.b16 {%0,%1,%2,%3}, [%4];" \
        : "=r"((r)[0]), "=r"((r)[1]), "=r"((r)[2]), "=r"((r)[3]) : "r"(addr))

#define LDMX4T(r, addr) \
    asm volatile("ldmatrix.sync.aligned.m8n8.x4.trans.shared.b16 {%0,%1,%2,%3}, [%4];" \
        : "=r"((r)[0]), "=r"((r)[1]), "=r"((r)[2]), "=r"((r)[3]) : "r"(addr))

// bf16 MMA (attention path)
__device__ __forceinline__ void mma16816(float* d, const uint32_t* a, const uint32_t* b) {
    asm volatile(
        "mma.sync.aligned.m16n8k16.row.col.f32.bf16.bf16.f32 "
        "{%0,%1,%2,%3}, {%4,%5,%6,%7}, {%8,%9}, {%0,%1,%2,%3};"
        : "+f"(d[0]), "+f"(d[1]), "+f"(d[2]), "+f"(d[3])
        : "r"(a[0]), "r"(a[1]), "r"(a[2]), "r"(a[3]), "r"(b[0]), "r"(b[1]));
}

// fp16 MMA (projection path, fp32 accumulate)
__device__ __forceinline__ void mma16816h(float* d, const uint32_t* a, const uint32_t* b) {
    asm volatile(
        "mma.sync.aligned.m16n8k16.row.col.f32.f16.f16.f32 "
        "{%0,%1,%2,%3}, {%4,%5,%6,%7}, {%8,%9}, {%0,%1,%2,%3};"
        : "+f"(d[0]), "+f"(d[1]), "+f"(d[2]), "+f"(d[3])
        : "r"(a[0]), "r"(a[1]), "r"(a[2]), "r"(a[3]), "r"(b[0]), "r"(b[1]));
}

#define CP16(dst, src) \
    asm volatile("cp.async.cg.shared.global [%0], [%1], 16;" \
        :: "r"(dst), "l"((const void*)(src)))

__device__ __forceinline__ uint32_t pack_bf16x2(float f0, float f1) {
    __nv_bfloat162 t = __floats2bfloat162_rn(f0, f1);   // x = f0 (low half)
    return *reinterpret_cast<uint32_t*>(&t);
}

// SW128 swizzle on byte offsets (rows are 128 B)
#define ASW(off) ((uint32_t)(off) ^ ((((uint32_t)(off)) >> 3) & 0x70u))

// ===========================================================================
// x -> fp16 (one float4 per thread)
// ===========================================================================
__global__ void __launch_bounds__(256) xsplit_kernel(const float* __restrict__ x)
{
    const int i = blockIdx.x * 256 + threadIdx.x;
    float4 v = ((const float4*)x)[i];
    __half2 h0 = __floats2half2_rn(v.x, v.y);
    __half2 h1 = __floats2half2_rn(v.z, v.w);
    ((__half2*)g_Xh)[i * 2 + 0] = h0;
    ((__half2*)g_Xh)[i * 2 + 1] = h1;
}

// ===========================================================================
// W -> transposed fp16: WT[p][f][c] = W_p[c][f]
// ===========================================================================
__global__ void __launch_bounds__(256) wsplit_kernel(
    const float* __restrict__ wq, const float* __restrict__ wk,
    const float* __restrict__ wv)
{
    const int idx = blockIdx.x * 256 + threadIdx.x;
    const int p = idx >> 18;
    const int f = (idx >> 9) & 511;
    const int c = idx & 511;
    const float* __restrict__ W = (p == 0) ? wq : (p == 1) ? wk : wv;
    g_Wh[idx] = __float2half(W[c * 512 + f]);
}

// ===========================================================================
// Projection via fp16 single-product mma.sync.  BK=32, depth-2 cp.async,
// 2 CTAs/SM.  Stage = [A|B], each 128 rows x 80 B pitch (64 B data + 16 pad).
// Grid 1-D: (which, n-tile) fastest for L2 A-reuse.
// ===========================================================================
#define TPITCH 80
#define TILE_B 10240
#define STAGE_B 20480
#define PROJ_SMEM 40960

__global__ void __launch_bounds__(256, 2) proj_mma_kernel(
    const float* __restrict__ bq, const float* __restrict__ bk,
    const float* __restrict__ bv)
{
    extern __shared__ char smc[];
    const uint32_t sb = smem_u32(smc);

    const int tid  = threadIdx.x;
    const int lane = tid & 31;
    const int wid  = tid >> 5;
    const int wm   = wid & 3;
    const int wn   = wid >> 2;

    const int bx    = blockIdx.x;
    const int which = bx % 3;
    const int n0    = ((bx / 3) & 3) * 128;
    const int m0    = (bx / 12) * 128;

    const __half* __restrict__ Wp = g_Wh + which * 262144;
    const float* __restrict__ bias = (which == 0) ? bq : (which == 1) ? bk : bv;
    __nv_bfloat16* __restrict__ outH = (which == 0) ? g_Qh : (which == 1) ? g_Kh : g_Vh;
    __nv_bfloat16* __restrict__ outL = (which == 0) ? g_Ql : (which == 1) ? g_Kl : g_Vl;

    float acc[2][8][4];
#pragma unroll
    for (int a = 0; a < 2; a++)
#pragma unroll
        for (int b = 0; b < 8; b++)
#pragma unroll
            for (int c = 0; c < 4; c++) acc[a][b][c] = 0.0f;

    auto issue = [&](int c) {
        const int k0 = c * 32;
        const uint32_t st = sb + (c & 1) * STAGE_B;
#pragma unroll
        for (int i = 0; i < 2; i++) {
            const int slot = tid + i * 256;        // 0..511
            const int row  = slot >> 2;            // 0..127
            const int ch   = slot & 3;             // 16B chunk (8 fp16)
            const uint32_t off = row * TPITCH + ch * 16;
            CP16(st + off,          g_Xh + (m0 + row) * 512 + k0 + ch * 8);
            CP16(st + TILE_B + off, Wp   + (n0 + row) * 512 + k0 + ch * 8);
        }
        asm volatile("cp.async.commit_group;");
    };

    issue(0);
    for (int c = 0; c < 16; c++) {
        if (c < 15) {
            issue(c + 1);
            asm volatile("cp.async.wait_group 1;");
        } else {
            asm volatile("cp.async.wait_group 0;");
        }
        __syncthreads();

        const uint32_t st = sb + (c & 1) * STAGE_B;
#pragma unroll
        for (int ks = 0; ks < 2; ks++) {
            uint32_t af[2][4];
            const int al = lane & 15;
            const int ac = ks * 2 + (lane >> 4);
#pragma unroll
            for (int mt = 0; mt < 2; mt++) {
                const uint32_t ad = st + (wm * 32 + mt * 16 + al) * TPITCH + ac * 16;
                LDMX4(af[mt], ad);
            }
            const int br = (lane >> 4) * 8 + (lane & 7);
            const int bc = ks * 2 + ((lane >> 3) & 1);
#pragma unroll
            for (int p = 0; p < 4; p++) {
                const uint32_t bd = st + TILE_B
                                  + (wn * 64 + p * 16 + br) * TPITCH + bc * 16;
                uint32_t bh[4];
                LDMX4(bh, bd);
#pragma unroll
                for (int mt = 0; mt < 2; mt++) {
                    mma16816h(acc[mt][2 * p],     af[mt], &bh[0]);
                    mma16816h(acc[mt][2 * p + 1], af[mt], &bh[2]);
                }
            }
        }
        __syncthreads();
    }

    // ---- epilogue: bias, split hi/lo, scatter into [B][nh][W][H][d] ----
    const int g  = lane >> 2;
    const int tg = lane & 3;
#pragma unroll
    for (int mt = 0; mt < 2; mt++) {
#pragma unroll
        for (int half = 0; half < 2; half++) {
            const int pix = m0 + wm * 32 + mt * 16 + g + half * 8;
            const int b = pix >> 14;
            const int h = (pix >> 7) & 127;
            const int w = pix & 127;
#pragma unroll
            for (int nt = 0; nt < 8; nt++) {
                const int f  = n0 + wn * 64 + nt * 8 + tg * 2;
                const int nh = f >> 6;
                const int dd = f & 63;
                float2 bb = *(const float2*)(bias + f);
                const float ox = acc[mt][nt][half * 2 + 0] + bb.x;
                const float oy = acc[mt][nt][half * 2 + 1] + bb.y;
                __nv_bfloat16 hx = __float2bfloat16(ox);
                __nv_bfloat16 hy = __float2bfloat16(oy);
                __nv_bfloat162 hp; hp.x = hx; hp.y = hy;
                __nv_bfloat162 lp;
                lp.x = __float2bfloat16(ox - __bfloat162float(hx));
                lp.y = __float2bfloat16(oy - __bfloat162float(hy));
                const int off = (((b * 8 + nh) * 128 + w) * 128 + h) * 64 + dd;
                *(__nv_bfloat162*)(outH + off) = hp;
                *(__nv_bfloat162*)(outL + off) = lp;
            }
        }
    }
}

// ===========================================================================
// Tensor-core axial attention (unchanged — bf16 3-product, err ~1e-5).
// smem 96 KB: Qh 0, Ql 16K, Kh 32K, Kl 48K, Vh 64K, Vl 80K; SW128-swizzled.
// ===========================================================================
#define AQHI 0
#define AQLO 16384
#define AKHI 32768
#define AKLO 49152
#define AVHI 65536
#define AVLO 81920
#define ATTN_SMEM 98304

__global__ void __launch_bounds__(256, 2) attn_mma_kernel(float* __restrict__ out, const int stage)
{
    extern __shared__ char sm[];
    const uint32_t sb = smem_u32(sm);

    const int tid  = threadIdx.x;
    const int lane = tid & 31;
    const int wid  = tid >> 5;
    const int x_   = blockIdx.x;
    const int b8n  = blockIdx.z * 8 + blockIdx.y;

    const __nv_bfloat16* __restrict__ Vhp = (stage == 1) ? g_Vh : g_XVh;
    const __nv_bfloat16* __restrict__ Vlp = (stage == 1) ? g_Vl : g_XVl;

    int qbase, rstride;
    if (stage == 1) {
        qbase   = (b8n * 128 + x_) * 8192;
        rstride = 64;
    } else {
        qbase   = b8n * 1048576 + x_ * 64;
        rstride = 8192;
    }
    const int vbase = (b8n * 128 + x_) * 8192;

    // ---- group 0: Q,K tiles (needed for S) ----
    for (int idx = tid; idx < 1024; idx += 256) {
        const int row = idx >> 3;
        const int ch  = idx & 7;
        const int qoff = qbase + row * rstride + ch * 8;
        const uint32_t dst = ASW(row * 128 + ch * 16);
        CP16(sb + AQHI + dst, g_Qh + qoff);
        CP16(sb + AQLO + dst, g_Ql + qoff);
        CP16(sb + AKHI + dst, g_Kh + qoff);
        CP16(sb + AKLO + dst, g_Kl + qoff);
    }
    asm volatile("cp.async.commit_group;");
    // ---- group 1: V tiles (needed only for O) ----
    for (int idx = tid; idx < 1024; idx += 256) {
        const int row = idx >> 3;
        const int ch  = idx & 7;
        const int voff = vbase + row * 64 + ch * 8;
        const uint32_t dst = ASW(row * 128 + ch * 16);
        CP16(sb + AVHI + dst, Vhp + voff);
        CP16(sb + AVLO + dst, Vlp + voff);
    }
    asm volatile("cp.async.commit_group;");

    asm volatile("cp.async.wait_group 1;");   // Q,K ready; V may still fly
    __syncthreads();

    // ---- S = Q * K^T  (warp strip m16 x N=128), bf16x3 ----
    float sacc[16][4];
#pragma unroll
    for (int j = 0; j < 16; j++)
#pragma unroll
        for (int c = 0; c < 4; c++) sacc[j][c] = 0.0f;

    const int m0w = wid * 16;
    const int alr = lane & 15;
    const int alc = lane >> 4;
    const int blr = ((lane >> 4) << 3) + (lane & 7);
    const int blc = (lane >> 3) & 1;

#pragma unroll
    for (int kt = 0; kt < 4; kt++) {
        uint32_t ahi[4], alo[4];
        const uint32_t aa = sb + AQHI + ASW((m0w + alr) * 128 + (kt * 2 + alc) * 16);
        LDMX4(ahi, aa);
        LDMX4(alo, aa + (AQLO - AQHI));
#pragma unroll
        for (int p = 0; p < 8; p++) {
            const uint32_t ba = sb + AKHI + ASW((p * 16 + blr) * 128 + (kt * 2 + blc) * 16);
            uint32_t bh[4], bl[4];
            LDMX4(bh, ba);
            LDMX4(bl, ba + (AKLO - AKHI));
            mma16816(sacc[2 * p],     ahi, &bh[0]);
            mma16816(sacc[2 * p],     ahi, &bl[0]);
            mma16816(sacc[2 * p],     alo, &bh[0]);
            mma16816(sacc[2 * p + 1], ahi, &bh[2]);
            mma16816(sacc[2 * p + 1], ahi, &bl[2]);
            mma16816(sacc[2 * p + 1], alo, &bh[2]);
        }
    }

    // ---- clip(+-(1-eps)), /8, softmax per row, clip [eps,1-eps] ----
    {
        const float lo = -1.0f + EPSI, hi = 1.0f - EPSI;
#pragma unroll
        for (int j = 0; j < 16; j++)
#pragma unroll
            for (int c = 0; c < 4; c++)
                sacc[j][c] = fminf(fmaxf(sacc[j][c], lo), hi) * 0.125f;

        float mx0 = -1e30f, mx1 = -1e30f;
#pragma unroll
        for (int j = 0; j < 16; j++) {
            mx0 = fmaxf(mx0, fmaxf(sacc[j][0], sacc[j][1]));
            mx1 = fmaxf(mx1, fmaxf(sacc[j][2], sacc[j][3]));
        }
        mx0 = fmaxf(mx0, __shfl_xor_sync(0xffffffffu, mx0, 1));
        mx0 = fmaxf(mx0, __shfl_xor_sync(0xffffffffu, mx0, 2));
        mx1 = fmaxf(mx1, __shfl_xor_sync(0xffffffffu, mx1, 1));
        mx1 = fmaxf(mx1, __shfl_xor_sync(0xffffffffu, mx1, 2));

        float s0 = 0.0f, s1 = 0.0f;
#pragma unroll
        for (int j = 0; j < 16; j++) {
            sacc[j][0] = __expf(sacc[j][0] - mx0);
            sacc[j][1] = __expf(sacc[j][1] - mx0);
            sacc[j][2] = __expf(sacc[j][2] - mx1);
            sacc[j][3] = __expf(sacc[j][3] - mx1);
            s0 += sacc[j][0] + sacc[j][1];
            s1 += sacc[j][2] + sacc[j][3];
        }
        s0 += __shfl_xor_sync(0xffffffffu, s0, 1);
        s0 += __shfl_xor_sync(0xffffffffu, s0, 2);
        s1 += __shfl_xor_sync(0xffffffffu, s1, 1);
        s1 += __shfl_xor_sync(0xffffffffu, s1, 2);
        const float i0 = 1.0f / s0, i1 = 1.0f / s1;
        const float alo2 = EPSI, ahi2 = 1.0f - EPSI;
#pragma unroll
        for (int j = 0; j < 16; j++) {
            sacc[j][0] = fminf(fmaxf(sacc[j][0] * i0, alo2), ahi2);
            sacc[j][1] = fminf(fmaxf(sacc[j][1] * i0, alo2), ahi2);
            sacc[j][2] = fminf(fmaxf(sacc[j][2] * i1, alo2), ahi2);
            sacc[j][3] = fminf(fmaxf(sacc[j][3] * i1, alo2), ahi2);
        }
    }

    asm volatile("cp.async.wait_group 0;");   // V ready
    __syncthreads();

    // ---- O = P * V  (m16 x N=64, K=128); V via ldmatrix.trans ----
    float oacc[8][4];
#pragma unroll
    for (int j = 0; j < 8; j++)
#pragma unroll
        for (int c = 0; c < 4; c++) oacc[j][c] = 0.0f;

    const int vr = (lane & 7) + ((lane >> 3) & 1) * 8;
    const int vc = lane >> 4;

#pragma unroll
    for (int jj = 0; jj < 8; jj++) {
        const int e = 2 * jj, o = 2 * jj + 1;
        uint32_t phi[4], plo[4];
        {
            float p00 = sacc[e][0], p01 = sacc[e][1];
            float p02 = sacc[e][2], p03 = sacc[e][3];
            float p10 = sacc[o][0], p11 = sacc[o][1];
            float p12 = sacc[o][2], p13 = sacc[o][3];
            __nv_bfloat16 h;
            float r0, r1;
            phi[0] = pack_bf16x2(p00, p01);
            h = __float2bfloat16(p00); r0 = p00 - __bfloat162float(h);
            h = __float2bfloat16(p01); r1 = p01 - __bfloat162float(h);
            plo[0] = pack_bf16x2(r0, r1);
            phi[1] = pack_bf16x2(p02, p03);
            h = __float2bfloat16(p02); r0 = p02 - __bfloat162float(h);
            h = __float2bfloat16(p03); r1 = p03 - __bfloat162float(h);
            plo[1] = pack_bf16x2(r0, r1);
            phi[2] = pack_bf16x2(p10, p11);
            h = __float2bfloat16(p10); r0 = p10 - __bfloat162float(h);
            h = __float2bfloat16(p11); r1 = p11 - __bfloat162float(h);
            plo[2] = pack_bf16x2(r0, r1);
            phi[3] = pack_bf16x2(p12, p13);
            h = __float2bfloat16(p12); r0 = p12 - __bfloat162float(h);
            h = __float2bfloat16(p13); r1 = p13 - __bfloat162float(h);
            plo[3] = pack_bf16x2(r0, r1);
        }
#pragma unroll
        for (int np = 0; np < 4; np++) {
            const uint32_t ba = sb + AVHI
                + ASW((jj * 16 + vr) * 128 + np * 32 + vc * 16);
            uint32_t bh[4], bl[4];
            LDMX4T(bh, ba);
            LDMX4T(bl, ba + (AVLO - AVHI));
            mma16816(oacc[2 * np],     phi, &bh[0]);
            mma16816(oacc[2 * np],     phi, &bl[0]);
            mma16816(oacc[2 * np],     plo, &bh[0]);
            mma16816(oacc[2 * np + 1], phi, &bh[2]);
            mma16816(oacc[2 * np + 1], phi, &bl[2]);
            mma16816(oacc[2 * np + 1], plo, &bh[2]);
        }
    }

    // ---- epilogue ----
    const int g  = lane >> 2;
    const int t4 = lane & 3;
    if (stage == 1) {
        const int base = b8n * 1048576 + x_ * 64;
#pragma unroll
        for (int nt = 0; nt < 8; nt++) {
            const int d = nt * 8 + t4 * 2;
#pragma unroll
            for (int half = 0; half < 2; half++) {
                const float ox = oacc[nt][half * 2 + 0];
                const float oy = oacc[nt][half * 2 + 1];
                __nv_bfloat16 hx = __float2bfloat16(ox);
                __nv_bfloat16 hy = __float2bfloat16(oy);
                __nv_bfloat162 hp; hp.x = hx; hp.y = hy;
                __nv_bfloat162 lp;
                lp.x = __float2bfloat16(ox - __bfloat162float(hx));
                lp.y = __float2bfloat16(oy - __bfloat162float(hy));
                const int off = base + (m0w + g + half * 8) * 8192 + d;
                *(__nv_bfloat162*)(g_XVh + off) = hp;
                *(__nv_bfloat162*)(g_XVl + off) = lp;
            }
        }
    } else {
        const int n = b8n & 7;
        const int b = b8n >> 3;
        const int base = (b * 128 + x_) * 65536 + n;
#pragma unroll
        for (int nt = 0; nt < 8; nt++) {
            const int d = nt * 8 + t4 * 2;
            out[base + (m0w + g) * 512 + d * 8]           = oacc[nt][0];
            out[base + (m0w + g) * 512 + (d + 1) * 8]     = oacc[nt][1];
            out[base + (m0w + g + 8) * 512 + d * 8]       = oacc[nt][2];
            out[base + (m0w + g + 8) * 512 + (d + 1) * 8] = oacc[nt][3];
        }
    }
}

// ---------------------------------------------------------------------------
extern "C" void kernel_launch(void* const* d_in, const int* in_sizes, int n_in,
                              void* d_out, int out_size)
{
    const float* x  = (const float*)d_in[0];
    const float* wq = (const float*)d_in[1];
    const float* bq = (const float*)d_in[2];
    const float* wk = (const float*)d_in[3];
    const float* bk = (const float*)d_in[4];
    const float* wv = (const float*)d_in[5];
    const float* bv = (const float*)d_in[6];
    float* out = (float*)d_out;

    cudaFuncSetAttribute((const void*)attn_mma_kernel,
                         cudaFuncAttributeMaxDynamicSharedMemorySize, ATTN_SMEM);
    cudaFuncSetAttribute((const void*)proj_mma_kernel,
                         cudaFuncAttributeMaxDynamicSharedMemorySize, PROJ_SMEM);

    xsplit_kernel<<<32768, 256>>>(x);
    wsplit_kernel<<<3072, 256>>>(wq, wk, wv);

    // 6144 CTAs: which fastest, then n-tile, then m-tile (L2 A-reuse)
    proj_mma_kernel<<<6144, 256, PROJ_SMEM>>>(bq, bk, bv);

    dim3 ag(128, 8, 4);
    attn_mma_kernel<<<ag, 256, ATTN_SMEM>>>(out, 1);
    attn_mma_kernel<<<ag, 256, ATTN_SMEM>>>(out, 2);
}

// round 13
// speedup vs baseline: 2.1807x; 1.3009x over previous
#include <cuda_runtime.h>
#include <cuda_bf16.h>
#include <cuda_fp16.h>
#include <cstdint>

#define EPSI 1e-7f

// ===========================================================================
// Scratch (__device__ globals; no allocation allowed).
// Qf/Kf/Vf: fp16, [B][nh][W][H][d].   XVf: fp16, [B][nh][H][W][d].
// g_Xh: fp16 x, [pix][c].  g_Wh: fp16 W^T, [p][f][c].
// ===========================================================================
__device__ __half g_Qf[33554432];
__device__ __half g_Kf[33554432];
__device__ __half g_Vf[33554432];
__device__ __half g_XVf[33554432];
__device__ __half g_Xh[33554432];
__device__ __half g_Wh[786432];

// ===========================================================================
// Helpers (sm_80-era tensor path; compiles on plain compute_103 target)
// ===========================================================================
__device__ __forceinline__ uint32_t smem_u32(const void* p) {
    uint32_t a;
    asm("{ .reg .u64 t; cvta.to.shared.u64 t, %1; cvt.u32.u64 %0, t; }"
        : "=r"(a) : "l"(p));
    return a;
}

#define LDMX4(r, addr) \
    asm volatile("ldmatrix.sync.aligned.m8n8.x4.shared.b16 {%0,%1,%2,%3}, [%4];" \
        : "=r"((r)[0]), "=r"((r)[1]), "=r"((r)[2]), "=r"((r)[3]) : "r"(addr))

#define LDMX4T(r, addr) \
    asm volatile("ldmatrix.sync.aligned.m8n8.x4.trans.shared.b16 {%0,%1,%2,%3}, [%4];" \
        : "=r"((r)[0]), "=r"((r)[1]), "=r"((r)[2]), "=r"((r)[3]) : "r"(addr))

// fp16 MMA, fp32 accumulate
__device__ __forceinline__ void mma16816h(float* d, const uint32_t* a, const uint32_t* b) {
    asm volatile(
        "mma.sync.aligned.m16n8k16.row.col.f32.f16.f16.f32 "
        "{%0,%1,%2,%3}, {%4,%5,%6,%7}, {%8,%9}, {%0,%1,%2,%3};"
        : "+f"(d[0]), "+f"(d[1]), "+f"(d[2]), "+f"(d[3])
        : "r"(a[0]), "r"(a[1]), "r"(a[2]), "r"(a[3]), "r"(b[0]), "r"(b[1]));
}

#define CP16(dst, src) \
    asm volatile("cp.async.cg.shared.global [%0], [%1], 16;" \
        :: "r"(dst), "l"((const void*)(src)))

__device__ __forceinline__ uint32_t pack_h2(float f0, float f1) {
    __half2 t = __floats2half2_rn(f0, f1);   // x = f0 (low half)
    return *reinterpret_cast<uint32_t*>(&t);
}

// SW128 swizzle on byte offsets (rows are 128 B)
#define ASW(off) ((uint32_t)(off) ^ ((((uint32_t)(off)) >> 3) & 0x70u))

// ===========================================================================
// x -> fp16 (one float4 per thread)
// ===========================================================================
__global__ void __launch_bounds__(256) xsplit_kernel(const float* __restrict__ x)
{
    const int i = blockIdx.x * 256 + threadIdx.x;
    float4 v = ((const float4*)x)[i];
    ((__half2*)g_Xh)[i * 2 + 0] = __floats2half2_rn(v.x, v.y);
    ((__half2*)g_Xh)[i * 2 + 1] = __floats2half2_rn(v.z, v.w);
}

// ===========================================================================
// W -> transposed fp16: WT[p][f][c] = W_p[c][f]
// ===========================================================================
__global__ void __launch_bounds__(256) wsplit_kernel(
    const float* __restrict__ wq, const float* __restrict__ wk,
    const float* __restrict__ wv)
{
    const int idx = blockIdx.x * 256 + threadIdx.x;
    const int p = idx >> 18;
    const int f = (idx >> 9) & 511;
    const int c = idx & 511;
    const float* __restrict__ W = (p == 0) ? wq : (p == 1) ? wk : wv;
    g_Wh[idx] = __float2half(W[c * 512 + f]);
}

// ===========================================================================
// Projection via fp16 single-product mma.sync.  BK=32, depth-2 cp.async,
// 2 CTAs/SM.  Stage = [A|B], each 128 rows x 80 B pitch.
// Grid 1-D: (which, n-tile) fastest for L2 A-reuse.
// ===========================================================================
#define TPITCH 80
#define TILE_B 10240
#define STAGE_B 20480
#define PROJ_SMEM 40960

__global__ void __launch_bounds__(256, 2) proj_mma_kernel(
    const float* __restrict__ bq, const float* __restrict__ bk,
    const float* __restrict__ bv)
{
    extern __shared__ char smc[];
    const uint32_t sb = smem_u32(smc);

    const int tid  = threadIdx.x;
    const int lane = tid & 31;
    const int wid  = tid >> 5;
    const int wm   = wid & 3;
    const int wn   = wid >> 2;

    const int bx    = blockIdx.x;
    const int which = bx % 3;
    const int n0    = ((bx / 3) & 3) * 128;
    const int m0    = (bx / 12) * 128;

    const __half* __restrict__ Wp = g_Wh + which * 262144;
    const float* __restrict__ bias = (which == 0) ? bq : (which == 1) ? bk : bv;
    __half* __restrict__ outp = (which == 0) ? g_Qf : (which == 1) ? g_Kf : g_Vf;

    float acc[2][8][4];
#pragma unroll
    for (int a = 0; a < 2; a++)
#pragma unroll
        for (int b = 0; b < 8; b++)
#pragma unroll
            for (int c = 0; c < 4; c++) acc[a][b][c] = 0.0f;

    auto issue = [&](int c) {
        const int k0 = c * 32;
        const uint32_t st = sb + (c & 1) * STAGE_B;
#pragma unroll
        for (int i = 0; i < 2; i++) {
            const int slot = tid + i * 256;        // 0..511
            const int row  = slot >> 2;            // 0..127
            const int ch   = slot & 3;             // 16B chunk (8 fp16)
            const uint32_t off = row * TPITCH + ch * 16;
            CP16(st + off,          g_Xh + (m0 + row) * 512 + k0 + ch * 8);
            CP16(st + TILE_B + off, Wp   + (n0 + row) * 512 + k0 + ch * 8);
        }
        asm volatile("cp.async.commit_group;");
    };

    issue(0);
    for (int c = 0; c < 16; c++) {
        if (c < 15) {
            issue(c + 1);
            asm volatile("cp.async.wait_group 1;");
        } else {
            asm volatile("cp.async.wait_group 0;");
        }
        __syncthreads();

        const uint32_t st = sb + (c & 1) * STAGE_B;
#pragma unroll
        for (int ks = 0; ks < 2; ks++) {
            uint32_t af[2][4];
            const int al = lane & 15;
            const int ac = ks * 2 + (lane >> 4);
#pragma unroll
            for (int mt = 0; mt < 2; mt++) {
                const uint32_t ad = st + (wm * 32 + mt * 16 + al) * TPITCH + ac * 16;
                LDMX4(af[mt], ad);
            }
            const int br = (lane >> 4) * 8 + (lane & 7);
            const int bc = ks * 2 + ((lane >> 3) & 1);
#pragma unroll
            for (int p = 0; p < 4; p++) {
                const uint32_t bd = st + TILE_B
                                  + (wn * 64 + p * 16 + br) * TPITCH + bc * 16;
                uint32_t bh[4];
                LDMX4(bh, bd);
#pragma unroll
                for (int mt = 0; mt < 2; mt++) {
                    mma16816h(acc[mt][2 * p],     af[mt], &bh[0]);
                    mma16816h(acc[mt][2 * p + 1], af[mt], &bh[2]);
                }
            }
        }
        __syncthreads();
    }

    // ---- epilogue: bias, convert fp16, scatter into [B][nh][W][H][d] ----
    const int g  = lane >> 2;
    const int tg = lane & 3;
#pragma unroll
    for (int mt = 0; mt < 2; mt++) {
#pragma unroll
        for (int half = 0; half < 2; half++) {
            const int pix = m0 + wm * 32 + mt * 16 + g + half * 8;
            const int b = pix >> 14;
            const int h = (pix >> 7) & 127;
            const int w = pix & 127;
#pragma unroll
            for (int nt = 0; nt < 8; nt++) {
                const int f  = n0 + wn * 64 + nt * 8 + tg * 2;
                const int nh = f >> 6;
                const int dd = f & 63;
                float2 bb = *(const float2*)(bias + f);
                const float ox = acc[mt][nt][half * 2 + 0] + bb.x;
                const float oy = acc[mt][nt][half * 2 + 1] + bb.y;
                const int off = (((b * 8 + nh) * 128 + w) * 128 + h) * 64 + dd;
                *(__half2*)(outp + off) = __floats2half2_rn(ox, oy);
            }
        }
    }
}

// ===========================================================================
// Tensor-core axial attention — fp16 single-product.
// smem 48 KB: Q 0, K 16K, V 32K; 128 rows x 128 B, SW128-swizzled.
// ===========================================================================
#define AQ 0
#define AK 16384
#define AV 32768
#define ATTN_SMEM 49152

__global__ void __launch_bounds__(256, 2) attn_mma_kernel(float* __restrict__ out, const int stage)
{
    extern __shared__ char sm[];
    const uint32_t sb = smem_u32(sm);

    const int tid  = threadIdx.x;
    const int lane = tid & 31;
    const int wid  = tid >> 5;
    const int x_   = blockIdx.x;
    const int b8n  = blockIdx.z * 8 + blockIdx.y;

    const __half* __restrict__ Vp = (stage == 1) ? g_Vf : g_XVf;

    int qbase, rstride;
    if (stage == 1) {
        qbase   = (b8n * 128 + x_) * 8192;
        rstride = 64;
    } else {
        qbase   = b8n * 1048576 + x_ * 64;
        rstride = 8192;
    }
    const int vbase = (b8n * 128 + x_) * 8192;

    // ---- group 0: Q,K tiles ----
    for (int idx = tid; idx < 1024; idx += 256) {
        const int row = idx >> 3;
        const int ch  = idx & 7;
        const int qoff = qbase + row * rstride + ch * 8;
        const uint32_t dst = ASW(row * 128 + ch * 16);
        CP16(sb + AQ + dst, g_Qf + qoff);
        CP16(sb + AK + dst, g_Kf + qoff);
    }
    asm volatile("cp.async.commit_group;");
    // ---- group 1: V tile ----
    for (int idx = tid; idx < 1024; idx += 256) {
        const int row = idx >> 3;
        const int ch  = idx & 7;
        const uint32_t dst = ASW(row * 128 + ch * 16);
        CP16(sb + AV + dst, Vp + vbase + row * 64 + ch * 8);
    }
    asm volatile("cp.async.commit_group;");

    asm volatile("cp.async.wait_group 1;");   // Q,K ready; V may still fly
    __syncthreads();

    // ---- S = Q * K^T  (warp strip m16 x N=128) ----
    float sacc[16][4];
#pragma unroll
    for (int j = 0; j < 16; j++)
#pragma unroll
        for (int c = 0; c < 4; c++) sacc[j][c] = 0.0f;

    const int m0w = wid * 16;
    const int alr = lane & 15;
    const int alc = lane >> 4;
    const int blr = ((lane >> 4) << 3) + (lane & 7);
    const int blc = (lane >> 3) & 1;

#pragma unroll
    for (int kt = 0; kt < 4; kt++) {
        uint32_t af[4];
        const uint32_t aa = sb + AQ + ASW((m0w + alr) * 128 + (kt * 2 + alc) * 16);
        LDMX4(af, aa);
#pragma unroll
        for (int p = 0; p < 8; p++) {
            const uint32_t ba = sb + AK + ASW((p * 16 + blr) * 128 + (kt * 2 + blc) * 16);
            uint32_t bh[4];
            LDMX4(bh, ba);
            mma16816h(sacc[2 * p],     af, &bh[0]);
            mma16816h(sacc[2 * p + 1], af, &bh[2]);
        }
    }

    // ---- clip(+-(1-eps)), /8, softmax per row, clip [eps,1-eps] ----
    {
        const float lo = -1.0f + EPSI, hi = 1.0f - EPSI;
#pragma unroll
        for (int j = 0; j < 16; j++)
#pragma unroll
            for (int c = 0; c < 4; c++)
                sacc[j][c] = fminf(fmaxf(sacc[j][c], lo), hi) * 0.125f;

        float mx0 = -1e30f, mx1 = -1e30f;
#pragma unroll
        for (int j = 0; j < 16; j++) {
            mx0 = fmaxf(mx0, fmaxf(sacc[j][0], sacc[j][1]));
            mx1 = fmaxf(mx1, fmaxf(sacc[j][2], sacc[j][3]));
        }
        mx0 = fmaxf(mx0, __shfl_xor_sync(0xffffffffu, mx0, 1));
        mx0 = fmaxf(mx0, __shfl_xor_sync(0xffffffffu, mx0, 2));
        mx1 = fmaxf(mx1, __shfl_xor_sync(0xffffffffu, mx1, 1));
        mx1 = fmaxf(mx1, __shfl_xor_sync(0xffffffffu, mx1, 2));

        float s0 = 0.0f, s1 = 0.0f;
#pragma unroll
        for (int j = 0; j < 16; j++) {
            sacc[j][0] = __expf(sacc[j][0] - mx0);
            sacc[j][1] = __expf(sacc[j][1] - mx0);
            sacc[j][2] = __expf(sacc[j][2] - mx1);
            sacc[j][3] = __expf(sacc[j][3] - mx1);
            s0 += sacc[j][0] + sacc[j][1];
            s1 += sacc[j][2] + sacc[j][3];
        }
        s0 += __shfl_xor_sync(0xffffffffu, s0, 1);
        s0 += __shfl_xor_sync(0xffffffffu, s0, 2);
        s1 += __shfl_xor_sync(0xffffffffu, s1, 1);
        s1 += __shfl_xor_sync(0xffffffffu, s1, 2);
        const float i0 = 1.0f / s0, i1 = 1.0f / s1;
        const float alo2 = EPSI, ahi2 = 1.0f - EPSI;
#pragma unroll
        for (int j = 0; j < 16; j++) {
            sacc[j][0] = fminf(fmaxf(sacc[j][0] * i0, alo2), ahi2);
            sacc[j][1] = fminf(fmaxf(sacc[j][1] * i0, alo2), ahi2);
            sacc[j][2] = fminf(fmaxf(sacc[j][2] * i1, alo2), ahi2);
            sacc[j][3] = fminf(fmaxf(sacc[j][3] * i1, alo2), ahi2);
        }
    }

    asm volatile("cp.async.wait_group 0;");   // V ready
    __syncthreads();

    // ---- O = P * V  (m16 x N=64, K=128); V via ldmatrix.trans ----
    float oacc[8][4];
#pragma unroll
    for (int j = 0; j < 8; j++)
#pragma unroll
        for (int c = 0; c < 4; c++) oacc[j][c] = 0.0f;

    const int vr = (lane & 7) + ((lane >> 3) & 1) * 8;
    const int vc = lane >> 4;

#pragma unroll
    for (int jj = 0; jj < 8; jj++) {
        const int e = 2 * jj, o = 2 * jj + 1;
        uint32_t pf[4];
        pf[0] = pack_h2(sacc[e][0], sacc[e][1]);
        pf[1] = pack_h2(sacc[e][2], sacc[e][3]);
        pf[2] = pack_h2(sacc[o][0], sacc[o][1]);
        pf[3] = pack_h2(sacc[o][2], sacc[o][3]);
#pragma unroll
        for (int np = 0; np < 4; np++) {
            const uint32_t ba = sb + AV
                + ASW((jj * 16 + vr) * 128 + np * 32 + vc * 16);
            uint32_t bh[4];
            LDMX4T(bh, ba);
            mma16816h(oacc[2 * np],     pf, &bh[0]);
            mma16816h(oacc[2 * np + 1], pf, &bh[2]);
        }
    }

    // ---- epilogue ----
    const int g  = lane >> 2;
    const int t4 = lane & 3;
    if (stage == 1) {
        // XV fp16 [b][n][h][w][d]: row = h, col = d, w = x_
        const int base = b8n * 1048576 + x_ * 64;
#pragma unroll
        for (int nt = 0; nt < 8; nt++) {
            const int d = nt * 8 + t4 * 2;
            const int off0 = base + (m0w + g) * 8192 + d;
            const int off1 = base + (m0w + g + 8) * 8192 + d;
            *(__half2*)(g_XVf + off0) = __floats2half2_rn(oacc[nt][0], oacc[nt][1]);
            *(__half2*)(g_XVf + off1) = __floats2half2_rn(oacc[nt][2], oacc[nt][3]);
        }
    } else {
        // out[b][h=x_][w=row][c=d*8+n]
        const int n = b8n & 7;
        const int b = b8n >> 3;
        const int base = (b * 128 + x_) * 65536 + n;
#pragma unroll
        for (int nt = 0; nt < 8; nt++) {
            const int d = nt * 8 + t4 * 2;
            out[base + (m0w + g) * 512 + d * 8]           = oacc[nt][0];
            out[base + (m0w + g) * 512 + (d + 1) * 8]     = oacc[nt][1];
            out[base + (m0w + g + 8) * 512 + d * 8]       = oacc[nt][2];
            out[base + (m0w + g + 8) * 512 + (d + 1) * 8] = oacc[nt][3];
        }
    }
}

// ---------------------------------------------------------------------------
extern "C" void kernel_launch(void* const* d_in, const int* in_sizes, int n_in,
                              void* d_out, int out_size)
{
    const float* x  = (const float*)d_in[0];
    const float* wq = (const float*)d_in[1];
    const float* bq = (const float*)d_in[2];
    const float* wk = (const float*)d_in[3];
    const float* bk = (const float*)d_in[4];
    const float* wv = (const float*)d_in[5];
    const float* bv = (const float*)d_in[6];
    float* out = (float*)d_out;

    cudaFuncSetAttribute((const void*)attn_mma_kernel,
                         cudaFuncAttributeMaxDynamicSharedMemorySize, ATTN_SMEM);
    cudaFuncSetAttribute((const void*)proj_mma_kernel,
                         cudaFuncAttributeMaxDynamicSharedMemorySize, PROJ_SMEM);

    xsplit_kernel<<<32768, 256>>>(x);
    wsplit_kernel<<<3072, 256>>>(wq, wk, wv);

    // 6144 CTAs: which fastest, then n-tile, then m-tile (L2 A-reuse)
    proj_mma_kernel<<<6144, 256, PROJ_SMEM>>>(bq, bk, bv);

    dim3 ag(128, 8, 4);
    attn_mma_kernel<<<ag, 256, ATTN_SMEM>>>(out, 1);
    attn_mma_kernel<<<ag, 256, ATTN_SMEM>>>(out, 2);
}